// round 2
// baseline (speedup 1.0000x reference)
#include <cuda_runtime.h>
#include <math_constants.h>

// Scratch for inter-kernel z (512 x 16). Overwritten fully every launch.
__device__ float g_z[512 * 16];

// ---- packed f32x2 helpers (Blackwell packed fp32 pipe, bit-exact fp32) ----
__device__ __forceinline__ unsigned long long pack2(float a, float b) {
    unsigned long long r;
    asm("mov.b64 %0, {%1, %2};" : "=l"(r) : "f"(a), "f"(b));
    return r;
}
__device__ __forceinline__ void unpack2(unsigned long long v, float& a, float& b) {
    asm("mov.b64 {%0, %1}, %2;" : "=f"(a), "=f"(b) : "l"(v));
}
__device__ __forceinline__ unsigned long long ffma2(unsigned long long a,
                                                    unsigned long long b,
                                                    unsigned long long c) {
    unsigned long long d;
    asm("fma.rn.f32x2 %0, %1, %2, %3;" : "=l"(d) : "l"(a), "l"(b), "l"(c));
    return d;
}

// ---------------------------------------------------------------------------
// Stage 1: each block handles TWO (b,p) pairs (bp = blockIdx.x*2 + u):
//   - signs s = sign(x.S1 - T1 - 1e-4), stored duplicated as (s,s) f32x2
//   - scores_g(k) = sum_j s_gj * H1[j,k] via FFMA2 (2 k per op)
//   - argmax over k (first occurrence), LUT1 gather, z accumulation
// Grid: 2048 blocks, 256 threads. Each thread owns 4 k per chunk, 4 chunks.
// ---------------------------------------------------------------------------
__global__ __launch_bounds__(256, 1)
void stage1_kernel(const float* __restrict__ x,
                   const float* __restrict__ S1,
                   const float* __restrict__ H1,
                   const float* __restrict__ T1,
                   const float* __restrict__ LUT1)
{
    __shared__ unsigned long long s_sm[2][456];  // duplicated signs per bp half
    __shared__ float rmax[2][10][8];
    __shared__ int   ridx[2][10][8];
    __shared__ int   fidx[2][10];

    const int bp0 = blockIdx.x * 2;              // first bp pair of this block
    const int tid = threadIdx.x;

    // ---- signs for both halves ----
    for (int f = tid; f < 900; f += 256) {
        const int u  = (f < 450) ? 0 : 1;
        const int e  = f - u * 450;
        const int c  = e / 15;
        const int k  = e - c * 15;
        const int bp = bp0 + u;
        const int b  = bp >> 3;
        const int p  = bp & 7;
        const float x0 = x[b * 480 + p * 60 + c * 2 + 0];
        const float x1 = x[b * 480 + p * 60 + c * 2 + 1];
        float v = x0 * S1[(c * 2 + 0) * 15 + k];
        v = fmaf(x1, S1[(c * 2 + 1) * 15 + k], v);
        v = v - T1[c * 15 + k];
        v = v - 1e-4f;
        const float s = (v > 0.0f) ? 1.0f : ((v < 0.0f) ? -1.0f : 0.0f);
        s_sm[u][e] = pack2(s, s);
    }
    __syncthreads();

    // ---- main scores + per-thread argmax ----
    float bmax[2][10];
    int   bidx[2][10];
#pragma unroll
    for (int u = 0; u < 2; u++)
#pragma unroll
        for (int g = 0; g < 10; g++) { bmax[u][g] = -CUDART_INF_F; bidx[u][g] = 0; }

#pragma unroll 1
    for (int chunk = 0; chunk < 4; chunk++) {
        const int k0 = chunk * 1024 + tid * 4;
        unsigned long long acc[2][10][2];
#pragma unroll
        for (int u = 0; u < 2; u++)
#pragma unroll
            for (int g = 0; g < 10; g++) { acc[u][g][0] = 0ull; acc[u][g][1] = 0ull; }

        const float* h1p = H1 + k0;
#pragma unroll 5
        for (int j = 0; j < 45; j++) {
            const ulonglong2 hv =
                *reinterpret_cast<const ulonglong2*>(h1p + (size_t)j * 4096);
#pragma unroll
            for (int u = 0; u < 2; u++) {
#pragma unroll
                for (int g = 0; g < 10; g++) {
                    const unsigned long long s2 = s_sm[u][g * 45 + j];
                    acc[u][g][0] = ffma2(s2, hv.x, acc[u][g][0]);
                    acc[u][g][1] = ffma2(s2, hv.y, acc[u][g][1]);
                }
            }
        }

        // k ascending (lo lane = even k); strict > keeps first occurrence,
        // matching jnp.argmax semantics.
#pragma unroll
        for (int u = 0; u < 2; u++) {
#pragma unroll
            for (int g = 0; g < 10; g++) {
                float v0, v1, v2, v3;
                unpack2(acc[u][g][0], v0, v1);
                unpack2(acc[u][g][1], v2, v3);
                if (v0 > bmax[u][g]) { bmax[u][g] = v0; bidx[u][g] = k0 + 0; }
                if (v1 > bmax[u][g]) { bmax[u][g] = v1; bidx[u][g] = k0 + 1; }
                if (v2 > bmax[u][g]) { bmax[u][g] = v2; bidx[u][g] = k0 + 2; }
                if (v3 > bmax[u][g]) { bmax[u][g] = v3; bidx[u][g] = k0 + 3; }
            }
        }
    }

    // ---- warp argmax reduce (value desc, index asc on ties) ----
#pragma unroll
    for (int u = 0; u < 2; u++) {
#pragma unroll
        for (int g = 0; g < 10; g++) {
#pragma unroll
            for (int off = 16; off > 0; off >>= 1) {
                const float ov = __shfl_down_sync(0xffffffffu, bmax[u][g], off);
                const int   oi = __shfl_down_sync(0xffffffffu, bidx[u][g], off);
                if (ov > bmax[u][g] || (ov == bmax[u][g] && oi < bidx[u][g])) {
                    bmax[u][g] = ov; bidx[u][g] = oi;
                }
            }
        }
    }
    const int wid = tid >> 5;
    if ((tid & 31) == 0) {
#pragma unroll
        for (int u = 0; u < 2; u++)
#pragma unroll
            for (int g = 0; g < 10; g++) {
                rmax[u][g][wid] = bmax[u][g];
                ridx[u][g][wid] = bidx[u][g];
            }
    }
    __syncthreads();

    // ---- cross-warp reduce: 20 threads, one (u,g) each ----
    if (tid < 20) {
        const int u = tid / 10;
        const int g = tid - u * 10;
        float bv = rmax[u][g][0];
        int   bi = ridx[u][g][0];
#pragma unroll
        for (int w = 1; w < 8; w++) {
            const float ov = rmax[u][g][w];
            const int   oi = ridx[u][g][w];
            if (ov > bv || (ov == bv && oi < bi)) { bv = ov; bi = oi; }
        }
        fidx[u][g] = bi;
    }
    __syncthreads();

    // ---- LUT1 gather + z accumulation (2 threads, one bp each) ----
    if (tid < 2) {
        const int u  = tid;
        const int bp = bp0 + u;
        const int b  = bp >> 3;
        const int p  = bp & 7;
        float z0 = 0.0f, z1 = 0.0f;
#pragma unroll
        for (int g = 0; g < 10; g++) {
            const int idx = fidx[u][g];
            z0 += LUT1[(g * 4096 + idx) * 2 + 0];
            z1 += LUT1[(g * 4096 + idx) * 2 + 1];
        }
        g_z[b * 16 + p * 2 + 0] = z0;
        g_z[b * 16 + p * 2 + 1] = z1;
    }
}

// ---------------------------------------------------------------------------
// Stage 2: per batch row:
//   w = sign(z.S2 - T2) (0 -> -1), scores16 = w.H2, argmax over 16,
//   logits = sum_c LUT2[c][idx2_c][:], out = log_softmax(logits)
// Grid: 512 blocks, 128 threads.
// ---------------------------------------------------------------------------
__global__ __launch_bounds__(128, 8)
void stage2_kernel(const float* __restrict__ S2,
                   const float* __restrict__ H2,
                   const float* __restrict__ T2,
                   const float* __restrict__ LUT2,
                   float* __restrict__ out)
{
    __shared__ float z[16];
    __shared__ int   sidx[8];
    __shared__ float logits[100];
    __shared__ float s_lse;

    const int b   = blockIdx.x;
    const int tid = threadIdx.x;

    if (tid < 16) z[tid] = g_z[b * 16 + tid];
    __syncthreads();

    if (tid < 8) {
        const int c = tid;
        float w[15];
#pragma unroll
        for (int k = 0; k < 15; k++) {
            float v = z[2 * c + 0] * S2[(c * 2 + 0) * 15 + k];
            v = fmaf(z[2 * c + 1], S2[(c * 2 + 1) * 15 + k], v);
            v = v - T2[c * 15 + k];
            // where(v==0, -1, sign(v)) == (v > 0 ? 1 : -1)
            w[k] = (v > 0.0f) ? 1.0f : -1.0f;
        }
        float bm = -CUDART_INF_F;
        int   bi = 0;
#pragma unroll
        for (int m = 0; m < 16; m++) {
            float sc = 0.0f;
#pragma unroll
            for (int k = 0; k < 15; k++) sc = fmaf(w[k], H2[k * 16 + m], sc);
            if (sc > bm) { bm = sc; bi = m; }
        }
        sidx[c] = bi;
    }
    __syncthreads();

    if (tid < 100) {
        float l = 0.0f;
#pragma unroll
        for (int c = 0; c < 8; c++) l += LUT2[(c * 16 + sidx[c]) * 100 + tid];
        logits[tid] = l;
    }
    __syncthreads();

    if (tid == 0) {
        float mx = logits[0];
        for (int m = 1; m < 100; m++) mx = fmaxf(mx, logits[m]);
        float s = 0.0f;
        for (int m = 0; m < 100; m++) s += expf(logits[m] - mx);
        s_lse = mx + logf(s);
    }
    __syncthreads();

    if (tid < 100) out[b * 100 + tid] = logits[tid] - s_lse;
}

// ---------------------------------------------------------------------------
extern "C" void kernel_launch(void* const* d_in, const int* in_sizes, int n_in,
                              void* d_out, int out_size)
{
    const float* x    = (const float*)d_in[0];
    const float* S1   = (const float*)d_in[1];
    const float* H1   = (const float*)d_in[2];
    const float* T1   = (const float*)d_in[3];
    const float* LUT1 = (const float*)d_in[4];
    const float* S2   = (const float*)d_in[5];
    const float* H2   = (const float*)d_in[6];
    const float* T2   = (const float*)d_in[7];
    const float* LUT2 = (const float*)d_in[8];
    float* out = (float*)d_out;

    stage1_kernel<<<2048, 256>>>(x, S1, H1, T1, LUT1);
    stage2_kernel<<<512, 128>>>(S2, H2, T2, LUT2, out);
}

// round 4
// speedup vs baseline: 1.9831x; 1.9831x over previous
#include <cuda_runtime.h>
#include <cuda_bf16.h>
#include <math_constants.h>
#include <cstdint>

// ---------------- scratch (__device__ globals; no allocations) -------------
// A: signs, [40960 rows][144 cols] bf16  (cols = 3 repeats of 45 signs, pad to 48)
// BT: H1 3-term split, [4096 rows(n)][144 cols(k)] bf16 (t*48+k), pad zeros
__device__ __align__(16) __nv_bfloat16 g_A[40960 * 144];
__device__ __align__(16) __nv_bfloat16 g_BT[4096 * 144];
__device__ float g_pval[4][40960];
__device__ int   g_pidx[4][40960];
__device__ float g_z[512 * 16];

__device__ __forceinline__ uint32_t smem_u32(const void* p) {
    uint32_t a;
    asm("{ .reg .u64 t; cvta.to.shared.u64 t, %1; cvt.u32.u64 %0, t; }" : "=r"(a) : "l"(p));
    return a;
}

__device__ __forceinline__ void ldmatrix_x4(uint32_t* r, uint32_t addr) {
    asm volatile("ldmatrix.sync.aligned.m8n8.x4.shared.b16 {%0,%1,%2,%3}, [%4];"
                 : "=r"(r[0]), "=r"(r[1]), "=r"(r[2]), "=r"(r[3]) : "r"(addr));
}
__device__ __forceinline__ void ldmatrix_x2(uint32_t* r, uint32_t addr) {
    asm volatile("ldmatrix.sync.aligned.m8n8.x2.shared.b16 {%0,%1}, [%2];"
                 : "=r"(r[0]), "=r"(r[1]) : "r"(addr));
}
__device__ __forceinline__ void mma_bf16(float* c, const uint32_t* a, const uint32_t* b) {
    asm volatile(
        "mma.sync.aligned.m16n8k16.row.col.f32.bf16.bf16.f32 "
        "{%0,%1,%2,%3}, {%4,%5,%6,%7}, {%8,%9}, {%0,%1,%2,%3};"
        : "+f"(c[0]), "+f"(c[1]), "+f"(c[2]), "+f"(c[3])
        : "r"(a[0]), "r"(a[1]), "r"(a[2]), "r"(a[3]), "r"(b[0]), "r"(b[1]));
}

// ---------------------------------------------------------------------------
// Prep 1: signs -> g_A. Row (bp*10+g), col t*48+k = sign at j=g*45+k (k<45).
// ---------------------------------------------------------------------------
__global__ void prep_signs(const float* __restrict__ x,
                           const float* __restrict__ S1,
                           const float* __restrict__ T1)
{
    __shared__ float s_sm[456];
    const int bp  = blockIdx.x;
    const int tid = threadIdx.x;
    const float* xr = x + (bp >> 3) * 480 + (bp & 7) * 60;
    for (int f = tid; f < 450; f += 128) {
        const int c = f / 15, kk = f - c * 15;
        float v = xr[2 * c] * S1[(2 * c) * 15 + kk];
        v = fmaf(xr[2 * c + 1], S1[(2 * c + 1) * 15 + kk], v);
        v = v - T1[c * 15 + kk];
        v = v - 1e-4f;
        s_sm[f] = (v > 0.0f) ? 1.0f : ((v < 0.0f) ? -1.0f : 0.0f);
    }
    __syncthreads();
    for (int f = tid; f < 1440; f += 128) {
        const int g = f / 144, col = f - g * 144;
        const int t = col / 48, k = col - t * 48;
        (void)t;
        const float s = (k < 45) ? s_sm[g * 45 + k] : 0.0f;
        g_A[(size_t)(bp * 10 + g) * 144 + col] = __float2bfloat16(s);
    }
}

// ---------------------------------------------------------------------------
// Prep 2: 3-term exact bf16 split of H1^T into g_BT[n][t*48+k].
// ---------------------------------------------------------------------------
__global__ void prep_split(const float* __restrict__ H1)
{
    const int i = blockIdx.x * 256 + threadIdx.x;   // over 4096*144
    if (i >= 4096 * 144) return;
    const int n = i / 144, col = i - n * 144;
    const int t = col / 48, k = col - t * 48;
    float out = 0.0f;
    if (k < 45) {
        const float h  = H1[k * 4096 + n];
        const float a  = __bfloat162float(__float2bfloat16(h));
        const float r1 = h - a;
        const float b  = __bfloat162float(__float2bfloat16(r1));
        const float r2 = r1 - b;
        out = (t == 0) ? a : ((t == 1) ? r1 : r2);
        if (t == 1) out = b;          // bf16(r1) value
        if (t == 2) out = r2;         // rounded on store
    }
    g_BT[i] = __float2bfloat16(out);
}

// ---------------------------------------------------------------------------
// Main HMMA kernel. Grid 1280 = 320 M-blocks x 4 N-quarters, 256 threads.
// CTA tile 128M x 128N, K=144 (9 k-steps). A resident; B streamed 8 iters.
// Smem rows padded to 304 B (conflict-free ldmatrix with 12r mod 32 banks).
// ---------------------------------------------------------------------------
static constexpr int ROWB   = 304;                 // bytes per smem row (152 cols)
static constexpr int SM_A   = 0;
static constexpr int SM_B   = 128 * ROWB;          // 38912
static constexpr int SM_RED = 2 * 128 * ROWB;      // 77824
static constexpr int SMEM_BYTES = SM_RED + 4 * 128 * 8;  // + sval/sidx = 81920

__global__ __launch_bounds__(256, 1)
void mma_kernel()
{
    extern __shared__ __align__(16) char smem[];
    const uint32_t sb = smem_u32(smem);
    float* sval = reinterpret_cast<float*>(smem + SM_RED);
    int*   sidx = reinterpret_cast<int*>(smem + SM_RED + 2048);

    const int tid = threadIdx.x;
    const int wid = tid >> 5;
    const int l   = tid & 31;
    const int q   = l & 3;
    const int wx  = wid >> 2;          // 0..1 (M half)
    const int wy  = wid & 3;           // 0..3 (N quarter of tile)
    const int mb  = blockIdx.x >> 2;   // 0..319
    const int nq  = blockIdx.x & 3;    // 0..3

    // ---- load A tile (persistent): 128 rows x 288B ----
    {
        const size_t m0 = (size_t)mb * 128;
        for (int v = tid; v < 2304; v += 256) {
            const int row = v / 18, ch = v - row * 18;
            const uint4 d = *reinterpret_cast<const uint4*>(
                g_A + (m0 + row) * 144 + ch * 8);
            *reinterpret_cast<uint4*>(smem + SM_A + row * ROWB + ch * 16) = d;
        }
    }

    // ldmatrix base addresses (k advances +32B per k-step)
    uint32_t a_addr[4], b_addr[4];
#pragma unroll
    for (int mt = 0; mt < 4; mt++) {
        const int r = wx * 64 + mt * 16 + (l & 7) + 8 * ((l >> 3) & 1);
        a_addr[mt] = sb + SM_A + r * ROWB + (l >> 4) * 16;
    }
#pragma unroll
    for (int nt = 0; nt < 4; nt++) {
        const int n = wy * 32 + nt * 8 + (l & 7);
        b_addr[nt] = sb + SM_B + n * ROWB + ((l >> 3) & 1) * 16;
    }

    float rv[8];
    int   ri[8];
#pragma unroll
    for (int s = 0; s < 8; s++) { rv[s] = -CUDART_INF_F; ri[s] = 0; }

#pragma unroll 1
    for (int it = 0; it < 8; it++) {
        const int n0 = nq * 1024 + it * 128;

        // ---- load B tile ----
        for (int v = tid; v < 2304; v += 256) {
            const int row = v / 18, ch = v - row * 18;
            const uint4 d = *reinterpret_cast<const uint4*>(
                g_BT + (size_t)(n0 + row) * 144 + ch * 8);
            *reinterpret_cast<uint4*>(smem + SM_B + row * ROWB + ch * 16) = d;
        }
        __syncthreads();

        float acc[4][4][4];
#pragma unroll
        for (int mt = 0; mt < 4; mt++)
#pragma unroll
            for (int nt = 0; nt < 4; nt++) {
                acc[mt][nt][0] = 0.f; acc[mt][nt][1] = 0.f;
                acc[mt][nt][2] = 0.f; acc[mt][nt][3] = 0.f;
            }

#pragma unroll
        for (int ks = 0; ks < 9; ks++) {
            uint32_t af[4][4], bf[4][2];
#pragma unroll
            for (int mt = 0; mt < 4; mt++) ldmatrix_x4(af[mt], a_addr[mt] + ks * 32);
#pragma unroll
            for (int nt = 0; nt < 4; nt++) ldmatrix_x2(bf[nt], b_addr[nt] + ks * 32);
#pragma unroll
            for (int mt = 0; mt < 4; mt++)
#pragma unroll
                for (int nt = 0; nt < 4; nt++)
                    mma_bf16(acc[mt][nt], af[mt], bf[nt]);
        }

        // ---- running argmax from fragments ----
        // c0: (row l/4, col 2q), c1: +1 col, c2/c3: row +8.
#pragma unroll
        for (int mt = 0; mt < 4; mt++) {
#pragma unroll
            for (int nt = 0; nt < 4; nt++) {
                const int col0 = n0 + wy * 32 + nt * 8 + 2 * q;
                const int s0 = mt * 2, s1 = mt * 2 + 1;
                if (acc[mt][nt][0] > rv[s0]) { rv[s0] = acc[mt][nt][0]; ri[s0] = col0; }
                if (acc[mt][nt][1] > rv[s0]) { rv[s0] = acc[mt][nt][1]; ri[s0] = col0 + 1; }
                if (acc[mt][nt][2] > rv[s1]) { rv[s1] = acc[mt][nt][2]; ri[s1] = col0; }
                if (acc[mt][nt][3] > rv[s1]) { rv[s1] = acc[mt][nt][3]; ri[s1] = col0 + 1; }
            }
        }
        __syncthreads();   // B consumed; safe to overwrite next iter
    }

    // ---- reduce over the 4 lanes sharing each row (l%4), idx tiebreak ----
#pragma unroll
    for (int off = 1; off <= 2; off <<= 1) {
#pragma unroll
        for (int s = 0; s < 8; s++) {
            const float ov = __shfl_xor_sync(0xffffffffu, rv[s], off);
            const int   oi = __shfl_xor_sync(0xffffffffu, ri[s], off);
            if (ov > rv[s] || (ov == rv[s] && oi < ri[s])) { rv[s] = ov; ri[s] = oi; }
        }
    }
    if (q == 0) {
#pragma unroll
        for (int mt = 0; mt < 4; mt++) {
#pragma unroll
            for (int half = 0; half < 2; half++) {
                const int row = wx * 64 + mt * 16 + 8 * half + (l >> 2);
                sval[wy * 128 + row] = rv[mt * 2 + half];
                sidx[wy * 128 + row] = ri[mt * 2 + half];
            }
        }
    }
    __syncthreads();

    if (tid < 128) {
        float bv = sval[tid];
        int   bi = sidx[tid];
#pragma unroll
        for (int w = 1; w < 4; w++) {
            const float ov = sval[w * 128 + tid];
            const int   oi = sidx[w * 128 + tid];
            if (ov > bv || (ov == bv && oi < bi)) { bv = ov; bi = oi; }
        }
        g_pval[nq][mb * 128 + tid] = bv;
        g_pidx[nq][mb * 128 + tid] = bi;
    }
}

// ---------------------------------------------------------------------------
// Merge partial argmaxes (4 N-quarters ascending), LUT1 gather, z.
// ---------------------------------------------------------------------------
__global__ void merge_z(const float* __restrict__ LUT1)
{
    const int bp = blockIdx.x * 256 + threadIdx.x;
    if (bp >= 4096) return;
    float z0 = 0.0f, z1 = 0.0f;
#pragma unroll
    for (int g = 0; g < 10; g++) {
        const int m = bp * 10 + g;
        float bv = g_pval[0][m];
        int   bi = g_pidx[0][m];
#pragma unroll
        for (int qq = 1; qq < 4; qq++) {
            const float v = g_pval[qq][m];
            if (v > bv) { bv = v; bi = g_pidx[qq][m]; }   // quarters ascending
        }
        z0 += LUT1[(g * 4096 + bi) * 2 + 0];
        z1 += LUT1[(g * 4096 + bi) * 2 + 1];
    }
    g_z[bp * 2 + 0] = z0;
    g_z[bp * 2 + 1] = z1;
}

// ---------------------------------------------------------------------------
// Stage 2 (validated in R1).
// ---------------------------------------------------------------------------
__global__ __launch_bounds__(128, 8)
void stage2_kernel(const float* __restrict__ S2,
                   const float* __restrict__ H2,
                   const float* __restrict__ T2,
                   const float* __restrict__ LUT2,
                   float* __restrict__ out)
{
    __shared__ float z[16];
    __shared__ int   sidx2[8];
    __shared__ float logits[100];
    __shared__ float s_lse;

    const int b   = blockIdx.x;
    const int tid = threadIdx.x;

    if (tid < 16) z[tid] = g_z[b * 16 + tid];
    __syncthreads();

    if (tid < 8) {
        const int c = tid;
        float w[15];
#pragma unroll
        for (int k = 0; k < 15; k++) {
            float v = z[2 * c + 0] * S2[(c * 2 + 0) * 15 + k];
            v = fmaf(z[2 * c + 1], S2[(c * 2 + 1) * 15 + k], v);
            v = v - T2[c * 15 + k];
            w[k] = (v > 0.0f) ? 1.0f : -1.0f;   // where(v==0,-1,sign(v))
        }
        float bm = -CUDART_INF_F;
        int   bi = 0;
#pragma unroll
        for (int m = 0; m < 16; m++) {
            float sc = 0.0f;
#pragma unroll
            for (int k = 0; k < 15; k++) sc = fmaf(w[k], H2[k * 16 + m], sc);
            if (sc > bm) { bm = sc; bi = m; }
        }
        sidx2[c] = bi;
    }
    __syncthreads();

    if (tid < 100) {
        float lsum = 0.0f;
#pragma unroll
        for (int c = 0; c < 8; c++) lsum += LUT2[(c * 16 + sidx2[c]) * 100 + tid];
        logits[tid] = lsum;
    }
    __syncthreads();

    if (tid == 0) {
        float mx = logits[0];
        for (int m = 1; m < 100; m++) mx = fmaxf(mx, logits[m]);
        float s = 0.0f;
        for (int m = 0; m < 100; m++) s += expf(logits[m] - mx);
        s_lse = mx + logf(s);
    }
    __syncthreads();

    if (tid < 100) out[b * 100 + tid] = logits[tid] - s_lse;
}

// ---------------------------------------------------------------------------
extern "C" void kernel_launch(void* const* d_in, const int* in_sizes, int n_in,
                              void* d_out, int out_size)
{
    const float* x    = (const float*)d_in[0];
    const float* S1   = (const float*)d_in[1];
    const float* H1   = (const float*)d_in[2];
    const float* T1   = (const float*)d_in[3];
    const float* LUT1 = (const float*)d_in[4];
    const float* S2   = (const float*)d_in[5];
    const float* H2   = (const float*)d_in[6];
    const float* T2   = (const float*)d_in[7];
    const float* LUT2 = (const float*)d_in[8];
    float* out = (float*)d_out;

    static bool attr_set = false;
    if (!attr_set) {
        cudaFuncSetAttribute(mma_kernel, cudaFuncAttributeMaxDynamicSharedMemorySize,
                             SMEM_BYTES);
        attr_set = true;
    }

    prep_signs<<<4096, 128>>>(x, S1, T1);
    prep_split<<<2304, 256>>>(H1);
    mma_kernel<<<1280, 256, SMEM_BYTES>>>();
    merge_z<<<16, 256>>>(LUT1);
    stage2_kernel<<<512, 128>>>(S2, H2, T2, LUT2, out);
}

// round 5
// speedup vs baseline: 3.6561x; 1.8436x over previous
#include <cuda_runtime.h>
#include <cuda_fp16.h>
#include <math_constants.h>
#include <cstdint>

// ---------------- scratch (__device__ globals; no allocations) -------------
// A: signs, [40960 rows][96 cols] fp16 (2 repeats of 45 signs, each pad to 48)
// BT: H1 2-term fp16 split, [4096 rows(n)][96 cols(k)], col t*48+k
__device__ __align__(16) __half g_A[40960 * 96];
__device__ __align__(16) __half g_BT[4096 * 96];
__device__ float g_pval[4][40960];
__device__ int   g_pidx[4][40960];
__device__ float g_z[512 * 16];

__device__ __forceinline__ uint32_t smem_u32(const void* p) {
    uint32_t a;
    asm("{ .reg .u64 t; cvta.to.shared.u64 t, %1; cvt.u32.u64 %0, t; }" : "=r"(a) : "l"(p));
    return a;
}
__device__ __forceinline__ void ldmatrix_x4(uint32_t* r, uint32_t addr) {
    asm volatile("ldmatrix.sync.aligned.m8n8.x4.shared.b16 {%0,%1,%2,%3}, [%4];"
                 : "=r"(r[0]), "=r"(r[1]), "=r"(r[2]), "=r"(r[3]) : "r"(addr));
}
__device__ __forceinline__ void ldmatrix_x2(uint32_t* r, uint32_t addr) {
    asm volatile("ldmatrix.sync.aligned.m8n8.x2.shared.b16 {%0,%1}, [%2];"
                 : "=r"(r[0]), "=r"(r[1]) : "r"(addr));
}
__device__ __forceinline__ void mma_f16(float* c, const uint32_t* a, const uint32_t* b) {
    asm volatile(
        "mma.sync.aligned.m16n8k16.row.col.f32.f16.f16.f32 "
        "{%0,%1,%2,%3}, {%4,%5,%6,%7}, {%8,%9}, {%0,%1,%2,%3};"
        : "+f"(c[0]), "+f"(c[1]), "+f"(c[2]), "+f"(c[3])
        : "r"(a[0]), "r"(a[1]), "r"(a[2]), "r"(a[3]), "r"(b[0]), "r"(b[1]));
}
__device__ __forceinline__ void cp16(uint32_t dst, const void* src) {
    asm volatile("cp.async.cg.shared.global [%0], [%1], 16;" :: "r"(dst), "l"(src));
}
#define CP_COMMIT() asm volatile("cp.async.commit_group;" ::: "memory")
#define CP_WAIT(n)  asm volatile("cp.async.wait_group %0;" :: "n"(n) : "memory")

// ---------------------------------------------------------------------------
// Prep 1: signs -> g_A. Row (bp*10+g), col t*48+k = sign at j=g*45+k (k<45).
// ---------------------------------------------------------------------------
__global__ void prep_signs(const float* __restrict__ x,
                           const float* __restrict__ S1,
                           const float* __restrict__ T1)
{
    __shared__ float s_sm[456];
    const int bp  = blockIdx.x;
    const int tid = threadIdx.x;
    const float* xr = x + (bp >> 3) * 480 + (bp & 7) * 60;
    for (int f = tid; f < 450; f += 128) {
        const int c = f / 15, kk = f - c * 15;
        float v = xr[2 * c] * S1[(2 * c) * 15 + kk];
        v = fmaf(xr[2 * c + 1], S1[(2 * c + 1) * 15 + kk], v);
        v = v - T1[c * 15 + kk];
        v = v - 1e-4f;
        s_sm[f] = (v > 0.0f) ? 1.0f : ((v < 0.0f) ? -1.0f : 0.0f);
    }
    __syncthreads();
    for (int f = tid; f < 960; f += 128) {
        const int g = f / 96, col = f - g * 96;
        const int k = col % 48;
        const float s = (k < 45) ? s_sm[g * 45 + k] : 0.0f;
        g_A[(size_t)(bp * 10 + g) * 96 + col] = __float2half_rn(s);
    }
}

// ---------------------------------------------------------------------------
// Prep 2: 2-term exact fp16 split of H1^T into g_BT[n][t*48+k].
//   term0 = fp16(h); term1 = fp16(h - term0)  (residual exact in fp32)
// ---------------------------------------------------------------------------
__global__ void prep_split(const float* __restrict__ H1)
{
    const int i = blockIdx.x * 256 + threadIdx.x;   // over 4096*96
    if (i >= 4096 * 96) return;
    const int n = i / 96, col = i - n * 96;
    const int t = col / 48, k = col - t * 48;
    __half out = __float2half_rn(0.0f);
    if (k < 45) {
        const float h = H1[k * 4096 + n];
        const __half a = __float2half_rn(h);
        if (t == 0) out = a;
        else        out = __float2half_rn(h - __half2float(a));
    }
    g_BT[i] = out;
}

// ---------------------------------------------------------------------------
// Main HMMA kernel. Grid 1280 = 320 M-blocks x 4 N-quarters, 256 threads.
// CTA tile 128M x 128N, K=96 (6 k-steps). A resident; B double-buffered via
// cp.async. Smem rows padded to 208 B (row stride 52 banks => 20 mod 32 per
// row => conflict-free ldmatrix).
// ---------------------------------------------------------------------------
static constexpr int ROWB    = 208;
static constexpr int TILE_B  = 128 * ROWB;             // 26624
static constexpr int SM_A    = 0;
static constexpr int SM_B    = TILE_B;                 // buf0; buf1 at +TILE_B
static constexpr int SM_RED  = 3 * TILE_B;             // 79872
static constexpr int SMEM_BYTES = SM_RED + 4096;       // + sval/sidx = 83968

__global__ __launch_bounds__(256, 2)
void mma_kernel()
{
    extern __shared__ __align__(16) char smem[];
    const uint32_t sb = smem_u32(smem);
    float* sval = reinterpret_cast<float*>(smem + SM_RED);
    int*   sidx = reinterpret_cast<int*>(smem + SM_RED + 2048);

    const int tid = threadIdx.x;
    const int wid = tid >> 5;
    const int l   = tid & 31;
    const int q   = l & 3;
    const int wx  = wid >> 2;          // 0..1 (M half)
    const int wy  = wid & 3;           // 0..3 (N quarter of tile)
    const int mb  = blockIdx.x >> 2;   // 0..319
    const int nq  = blockIdx.x & 3;    // 0..3

    // ---- prologue: A tile + B tile 0 via cp.async (one commit group) ----
    {
        const size_t m0 = (size_t)mb * 128;
#pragma unroll
        for (int i = 0; i < 6; i++) {
            const int v = tid + i * 256;           // 1536 chunks
            const int row = v / 12, ch = v - row * 12;
            cp16(sb + SM_A + row * ROWB + ch * 16, g_A + (m0 + row) * 96 + ch * 8);
        }
        const size_t n0 = (size_t)nq * 1024;
#pragma unroll
        for (int i = 0; i < 6; i++) {
            const int v = tid + i * 256;
            const int row = v / 12, ch = v - row * 12;
            cp16(sb + SM_B + row * ROWB + ch * 16, g_BT + (n0 + row) * 96 + ch * 8);
        }
        CP_COMMIT();
    }

    // ldmatrix base addresses (k advances +32B per k-step)
    uint32_t a_addr[4], b_addr[4];
#pragma unroll
    for (int mt = 0; mt < 4; mt++) {
        const int r = wx * 64 + mt * 16 + (l & 7) + 8 * ((l >> 3) & 1);
        a_addr[mt] = sb + SM_A + r * ROWB + (l >> 4) * 16;
    }
#pragma unroll
    for (int nt = 0; nt < 4; nt++) {
        const int n = wy * 32 + nt * 8 + (l & 7);
        b_addr[nt] = sb + SM_B + n * ROWB + ((l >> 3) & 1) * 16;
    }

    float rv[8];
    int   ri[8];
#pragma unroll
    for (int s = 0; s < 8; s++) { rv[s] = -CUDART_INF_F; ri[s] = 0; }

#pragma unroll 1
    for (int it = 0; it < 8; it++) {
        const int n0 = nq * 1024 + it * 128;

        // prefetch next B tile into the other buffer
        if (it < 7) {
            const size_t nn = (size_t)nq * 1024 + (it + 1) * 128;
            const uint32_t bufo = ((it + 1) & 1) * TILE_B;
#pragma unroll
            for (int i = 0; i < 6; i++) {
                const int v = tid + i * 256;
                const int row = v / 12, ch = v - row * 12;
                cp16(sb + SM_B + bufo + row * ROWB + ch * 16,
                     g_BT + (nn + row) * 96 + ch * 8);
            }
            CP_COMMIT();
            CP_WAIT(1);
        } else {
            CP_WAIT(0);
        }
        __syncthreads();

        const uint32_t boff = (it & 1) * TILE_B;

        float acc[4][4][4];
#pragma unroll
        for (int mt = 0; mt < 4; mt++)
#pragma unroll
            for (int nt = 0; nt < 4; nt++) {
                acc[mt][nt][0] = 0.f; acc[mt][nt][1] = 0.f;
                acc[mt][nt][2] = 0.f; acc[mt][nt][3] = 0.f;
            }

#pragma unroll
        for (int ks = 0; ks < 6; ks++) {
            uint32_t af[4][4], bf[4][2];
#pragma unroll
            for (int mt = 0; mt < 4; mt++) ldmatrix_x4(af[mt], a_addr[mt] + ks * 32);
#pragma unroll
            for (int nt = 0; nt < 4; nt++) ldmatrix_x2(bf[nt], b_addr[nt] + boff + ks * 32);
#pragma unroll
            for (int mt = 0; mt < 4; mt++)
#pragma unroll
                for (int nt = 0; nt < 4; nt++)
                    mma_f16(acc[mt][nt], af[mt], bf[nt]);
        }

        // running argmax from fragments (c0:(row l/4,col 2q), c1:+1col, c2/3:+8row)
#pragma unroll
        for (int mt = 0; mt < 4; mt++) {
#pragma unroll
            for (int nt = 0; nt < 4; nt++) {
                const int col0 = n0 + wy * 32 + nt * 8 + 2 * q;
                const int s0 = mt * 2, s1 = mt * 2 + 1;
                if (acc[mt][nt][0] > rv[s0]) { rv[s0] = acc[mt][nt][0]; ri[s0] = col0; }
                if (acc[mt][nt][1] > rv[s0]) { rv[s0] = acc[mt][nt][1]; ri[s0] = col0 + 1; }
                if (acc[mt][nt][2] > rv[s1]) { rv[s1] = acc[mt][nt][2]; ri[s1] = col0; }
                if (acc[mt][nt][3] > rv[s1]) { rv[s1] = acc[mt][nt][3]; ri[s1] = col0 + 1; }
            }
        }
        __syncthreads();   // compute done before next iter overwrites this buffer
    }

    // ---- reduce over the 4 lanes sharing each row, idx tiebreak ----
#pragma unroll
    for (int off = 1; off <= 2; off <<= 1) {
#pragma unroll
        for (int s = 0; s < 8; s++) {
            const float ov = __shfl_xor_sync(0xffffffffu, rv[s], off);
            const int   oi = __shfl_xor_sync(0xffffffffu, ri[s], off);
            if (ov > rv[s] || (ov == rv[s] && oi < ri[s])) { rv[s] = ov; ri[s] = oi; }
        }
    }
    if (q == 0) {
#pragma unroll
        for (int mt = 0; mt < 4; mt++) {
#pragma unroll
            for (int half = 0; half < 2; half++) {
                const int row = wx * 64 + mt * 16 + 8 * half + (l >> 2);
                sval[wy * 128 + row] = rv[mt * 2 + half];
                sidx[wy * 128 + row] = ri[mt * 2 + half];
            }
        }
    }
    __syncthreads();

    if (tid < 128) {
        float bv = sval[tid];
        int   bi = sidx[tid];
#pragma unroll
        for (int w = 1; w < 4; w++) {
            const float ov = sval[w * 128 + tid];
            const int   oi = sidx[w * 128 + tid];
            if (ov > bv || (ov == bv && oi < bi)) { bv = ov; bi = oi; }
        }
        g_pval[nq][mb * 128 + tid] = bv;
        g_pidx[nq][mb * 128 + tid] = bi;
    }
}

// ---------------------------------------------------------------------------
// Merge partial argmaxes (4 N-quarters ascending), LUT1 gather, z.
// ---------------------------------------------------------------------------
__global__ void merge_z(const float* __restrict__ LUT1)
{
    const int bp = blockIdx.x * 256 + threadIdx.x;
    if (bp >= 4096) return;
    float z0 = 0.0f, z1 = 0.0f;
#pragma unroll
    for (int g = 0; g < 10; g++) {
        const int m = bp * 10 + g;
        float bv = g_pval[0][m];
        int   bi = g_pidx[0][m];
#pragma unroll
        for (int qq = 1; qq < 4; qq++) {
            const float v = g_pval[qq][m];
            if (v > bv) { bv = v; bi = g_pidx[qq][m]; }   // quarters ascending
        }
        z0 += LUT1[(g * 4096 + bi) * 2 + 0];
        z1 += LUT1[(g * 4096 + bi) * 2 + 1];
    }
    g_z[bp * 2 + 0] = z0;
    g_z[bp * 2 + 1] = z1;
}

// ---------------------------------------------------------------------------
// Stage 2 (validated in R1/R4).
// ---------------------------------------------------------------------------
__global__ __launch_bounds__(128, 8)
void stage2_kernel(const float* __restrict__ S2,
                   const float* __restrict__ H2,
                   const float* __restrict__ T2,
                   const float* __restrict__ LUT2,
                   float* __restrict__ out)
{
    __shared__ float z[16];
    __shared__ int   sidx2[8];
    __shared__ float logits[100];
    __shared__ float s_lse;

    const int b   = blockIdx.x;
    const int tid = threadIdx.x;

    if (tid < 16) z[tid] = g_z[b * 16 + tid];
    __syncthreads();

    if (tid < 8) {
        const int c = tid;
        float w[15];
#pragma unroll
        for (int k = 0; k < 15; k++) {
            float v = z[2 * c + 0] * S2[(c * 2 + 0) * 15 + k];
            v = fmaf(z[2 * c + 1], S2[(c * 2 + 1) * 15 + k], v);
            v = v - T2[c * 15 + k];
            w[k] = (v > 0.0f) ? 1.0f : -1.0f;   // where(v==0,-1,sign(v))
        }
        float bm = -CUDART_INF_F;
        int   bi = 0;
#pragma unroll
        for (int m = 0; m < 16; m++) {
            float sc = 0.0f;
#pragma unroll
            for (int k = 0; k < 15; k++) sc = fmaf(w[k], H2[k * 16 + m], sc);
            if (sc > bm) { bm = sc; bi = m; }
        }
        sidx2[c] = bi;
    }
    __syncthreads();

    if (tid < 100) {
        float lsum = 0.0f;
#pragma unroll
        for (int c = 0; c < 8; c++) lsum += LUT2[(c * 16 + sidx2[c]) * 100 + tid];
        logits[tid] = lsum;
    }
    __syncthreads();

    if (tid == 0) {
        float mx = logits[0];
        for (int m = 1; m < 100; m++) mx = fmaxf(mx, logits[m]);
        float s = 0.0f;
        for (int m = 0; m < 100; m++) s += expf(logits[m] - mx);
        s_lse = mx + logf(s);
    }
    __syncthreads();

    if (tid < 100) out[b * 100 + tid] = logits[tid] - s_lse;
}

// ---------------------------------------------------------------------------
extern "C" void kernel_launch(void* const* d_in, const int* in_sizes, int n_in,
                              void* d_out, int out_size)
{
    const float* x    = (const float*)d_in[0];
    const float* S1   = (const float*)d_in[1];
    const float* H1   = (const float*)d_in[2];
    const float* T1   = (const float*)d_in[3];
    const float* LUT1 = (const float*)d_in[4];
    const float* S2   = (const float*)d_in[5];
    const float* H2   = (const float*)d_in[6];
    const float* T2   = (const float*)d_in[7];
    const float* LUT2 = (const float*)d_in[8];
    float* out = (float*)d_out;

    static bool attr_set = false;
    if (!attr_set) {
        cudaFuncSetAttribute(mma_kernel, cudaFuncAttributeMaxDynamicSharedMemorySize,
                             SMEM_BYTES);
        attr_set = true;
    }

    prep_signs<<<4096, 128>>>(x, S1, T1);
    prep_split<<<1536, 256>>>(H1);
    mma_kernel<<<1280, 256, SMEM_BYTES>>>();
    merge_z<<<16, 256>>>(LUT1);
    stage2_kernel<<<512, 128>>>(S2, H2, T2, LUT2, out);
}